// round 4
// baseline (speedup 1.0000x reference)
#include <cuda_runtime.h>
#include <math.h>
#include <stdint.h>

#define Sc 2048
#define Dc 1024
#define Hc 16
#define DKc 64
#define Mtot 4096

#define LOG2E_SCALE 0.18033688011112042f     // 0.125 * log2(e)
#define MASKVAL     (-1.4426950408889634e9f) // -1e9 * log2(e)

// Scratch
__device__ float gQ[2 * Hc * Sc * DKc];   // [b,h,s,dk]
__device__ float gK[2 * Hc * Sc * DKc];
__device__ float gV[2 * Hc * Sc * DKc];
__device__ float gA[Mtot * Dc];           // attn out, [b,s,h*dk]
__device__ int gMaskFlag[16 * 32];        // [qtile128][ktile64] all-ones flags

#define SW(k) ((((k) & 3) ^ (((k) >> 2) & 3)) << 3)

__device__ __forceinline__ uint32_t f2tf(float f) {
    uint32_t u;
    asm("cvt.rna.tf32.f32 %0, %1;" : "=r"(u) : "f"(f));
    return u;
}
__device__ __forceinline__ float fexp2(float x) {
    float r;
    asm("ex2.approx.f32 %0, %1;" : "=f"(r) : "f"(x));
    return r;
}
__device__ __forceinline__ void mma8(float* c, const uint32_t* a, uint32_t b0, uint32_t b1) {
    asm volatile(
        "mma.sync.aligned.m16n8k8.row.col.f32.tf32.tf32.f32 "
        "{%0,%1,%2,%3},{%4,%5,%6,%7},{%8,%9},{%0,%1,%2,%3};\n"
        : "+f"(c[0]), "+f"(c[1]), "+f"(c[2]), "+f"(c[3])
        : "r"(a[0]), "r"(a[1]), "r"(a[2]), "r"(a[3]), "r"(b0), "r"(b1));
}

// ---------------------------------------------------------------------------
// tf32 GEMM: C[m][n] = sum_k A[m][k]*W[n][k] + bias[n]
// 128x128 tile, BK=16, 256 threads, 8 warps (2m x 4n), warp tile 64x32.
// Double-buffered smem: one __syncthreads per k-iter; STS overlaps MMA.
// ---------------------------------------------------------------------------
template <bool HEAD>
__device__ __forceinline__ void gemm_tf32(const float* __restrict__ A,
                                          const float* __restrict__ W,
                                          const float* __restrict__ bias,
                                          float* __restrict__ C) {
    __shared__ uint32_t As[2][16 * 128];
    __shared__ uint32_t Bs[2][16 * 128];

    const int tid = threadIdx.x, lane = tid & 31, warp = tid >> 5;
    const int wm = warp >> 2, wn = warp & 3;
    const int e = lane >> 2, la = lane & 3;
    const int m0 = blockIdx.y * 128, n0 = blockIdx.x * 128;
    const int r = tid >> 2, q = tid & 3;

    const float* Ap = A + (size_t)(m0 + r) * Dc + 4 * q;
    const float* Wp = W + (size_t)(n0 + r) * Dc + 4 * q;

    float acc[4][4][4];
#pragma unroll
    for (int mi = 0; mi < 4; mi++)
#pragma unroll
        for (int ni = 0; ni < 4; ni++)
#pragma unroll
            for (int t = 0; t < 4; t++) acc[mi][ni][t] = 0.f;

    auto store_tile = [&](int st, float4 a0, float4 a1, float4 w0, float4 w1) {
        const float va0[4] = {a0.x, a0.y, a0.z, a0.w};
        const float va1[4] = {a1.x, a1.y, a1.z, a1.w};
        const float vw0[4] = {w0.x, w0.y, w0.z, w0.w};
        const float vw1[4] = {w1.x, w1.y, w1.z, w1.w};
#pragma unroll
        for (int j = 0; j < 4; j++) {
            const int k = 4 * q + j;
            const int sw = SW(k);
            As[st][k * 128 + (r ^ sw)] = f2tf(va0[j]);
            As[st][k * 128 + ((r + 64) ^ sw)] = f2tf(va1[j]);
            Bs[st][k * 128 + (r ^ sw)] = f2tf(vw0[j]);
            Bs[st][k * 128 + ((r + 64) ^ sw)] = f2tf(vw1[j]);
        }
    };

    // prologue: tile 0 -> stage 0
    store_tile(0,
               *(const float4*)(Ap), *(const float4*)(Ap + 64 * Dc),
               *(const float4*)(Wp), *(const float4*)(Wp + 64 * Dc));
    __syncthreads();

    const int NIT = Dc / 16;
#pragma unroll 4
    for (int it = 0; it < NIT; it++) {
        const int cur = it & 1;

        float4 na0, na1, nw0, nw1;
        const bool more = (it + 1 < NIT);
        if (more) {
            const int ko = (it + 1) * 16;
            na0 = *(const float4*)(Ap + ko);
            na1 = *(const float4*)(Ap + 64 * Dc + ko);
            nw0 = *(const float4*)(Wp + ko);
            nw1 = *(const float4*)(Wp + 64 * Dc + ko);
        }

#pragma unroll
        for (int ks = 0; ks < 2; ks++) {
            const int kb = 8 * ks;
            uint32_t af[4][4], bf[4][2];
#pragma unroll
            for (int mi = 0; mi < 4; mi++) {
                const int mr = 64 * wm + 16 * mi;
                af[mi][0] = As[cur][(kb + la) * 128 + ((mr + e) ^ SW(kb + la))];
                af[mi][1] = As[cur][(kb + la) * 128 + ((mr + e + 8) ^ SW(kb + la))];
                af[mi][2] = As[cur][(kb + la + 4) * 128 + ((mr + e) ^ SW(kb + la + 4))];
                af[mi][3] = As[cur][(kb + la + 4) * 128 + ((mr + e + 8) ^ SW(kb + la + 4))];
            }
#pragma unroll
            for (int ni = 0; ni < 4; ni++) {
                const int nc = 32 * wn + 8 * ni;
                bf[ni][0] = Bs[cur][(kb + la) * 128 + ((nc + e) ^ SW(kb + la))];
                bf[ni][1] = Bs[cur][(kb + la + 4) * 128 + ((nc + e) ^ SW(kb + la + 4))];
            }
#pragma unroll
            for (int mi = 0; mi < 4; mi++)
#pragma unroll
                for (int ni = 0; ni < 4; ni++)
                    mma8(acc[mi][ni], af[mi], bf[ni][0], bf[ni][1]);
        }

        if (more) store_tile(cur ^ 1, na0, na1, nw0, nw1);
        __syncthreads();
    }

#pragma unroll
    for (int mi = 0; mi < 4; mi++) {
#pragma unroll
        for (int ni = 0; ni < 4; ni++) {
            const int nc = n0 + 32 * wn + 8 * ni + 2 * la;
            const float b0 = bias[nc], b1 = bias[nc + 1];
#pragma unroll
            for (int half = 0; half < 2; half++) {
                const int mr = m0 + 64 * wm + 16 * mi + e + 8 * half;
                const float v0 = acc[mi][ni][2 * half] + b0;
                const float v1 = acc[mi][ni][2 * half + 1] + b1;
                if (HEAD) {
                    const int bb = mr >> 11;
                    const int s = mr & 2047;
                    const int h = nc >> 6, dk = nc & 63;
                    *(float2*)(C + (((size_t)(bb * Hc + h)) * Sc + s) * DKc + dk) =
                        make_float2(v0, v1);
                } else {
                    *(float2*)(C + (size_t)mr * Dc + nc) = make_float2(v0, v1);
                }
            }
        }
    }
}

__global__ __launch_bounds__(256, 2) void qkv_kernel(
    const float* __restrict__ X,
    const float* __restrict__ Wq, const float* __restrict__ bq,
    const float* __restrict__ Wk, const float* __restrict__ bk,
    const float* __restrict__ Wv, const float* __restrict__ bv) {
    const float* W = Wq;
    const float* bias = bq;
    float* out = gQ;
    if (blockIdx.z == 1) { W = Wk; bias = bk; out = gK; }
    else if (blockIdx.z == 2) { W = Wv; bias = bv; out = gV; }
    gemm_tf32<true>(X, W, bias, out);
}

__global__ __launch_bounds__(256, 2) void oproj_kernel(
    const float* __restrict__ Wo, const float* __restrict__ bo,
    float* __restrict__ out) {
    gemm_tf32<false>(gA, Wo, bo, out);
}

// ---------------------------------------------------------------------------
// Mask tile flags: flag = 1 iff the 128x64 mask tile is all nonzero.
// ---------------------------------------------------------------------------
__global__ __launch_bounds__(256) void mask_flags_kernel(const int* __restrict__ mask) {
    const int qt = blockIdx.x >> 5, kt = blockIdx.x & 31;
    const int tid = threadIdx.x;
    int ok = 1;
#pragma unroll
    for (int i = 0; i < 8; i++) {
        const int idx = tid + 256 * i;
        const int row = idx >> 4, c4 = (idx & 15) * 4;
        const int4 v = *(const int4*)(mask + (size_t)(qt * 128 + row) * Sc + kt * 64 + c4);
        ok &= (v.x != 0) & (v.y != 0) & (v.z != 0) & (v.w != 0);
    }
    ok = __syncthreads_and(ok);
    if (tid == 0) gMaskFlag[blockIdx.x] = ok;
}

// ---------------------------------------------------------------------------
// Flash attention, tf32 MMA. Block: 256 thr (8 warps), q-tile 128, kv-tile 64.
// Warp w owns q rows 16w..16w+15; Q a-frags pinned in registers.
// smem (u32): QsPs[8704] (Qs [dk64][q128] in prologue, Ps [q128][68] in loop)
//             Ks[4096]   ([dk64][kv64] swizzled)
//             Vs[4608]   ([kv64][72])
// Total 69632 B -> 2 CTAs/SM. P staging is warp-private -> __syncwarp only.
// ---------------------------------------------------------------------------
__global__ __launch_bounds__(256, 2) void flash_kernel(const int* __restrict__ mask) {
    extern __shared__ uint32_t smu[];
    uint32_t* QsPs = smu;                // 8704 u32
    uint32_t* Ks = smu + 8704;           // 4096 u32
    uint32_t* Vs = smu + 8704 + 4096;    // 4608 u32

    const int tid = threadIdx.x, lane = tid & 31, warp = tid >> 5;
    const int e = lane >> 2, la = lane & 3;
    const int qt = blockIdx.x, bh = blockIdx.y;
    const int q0 = qt * 128;

    const float* Qg = gQ + (size_t)bh * Sc * DKc + (size_t)q0 * DKc;
    const float* Kg = gK + (size_t)bh * Sc * DKc;
    const float* Vg = gV + (size_t)bh * Sc * DKc;

    // Load + transpose Q -> QsPs (scaled, tf32), [dk][128] swizzled
    {
        const int r = tid >> 2, qd = tid & 3;
#pragma unroll
        for (int half = 0; half < 2; half++) {
            const int row = r + 64 * half;
#pragma unroll
            for (int i = 0; i < 4; i++) {
                const int kq = qd + 4 * i;
                float4 v = *(const float4*)(Qg + (size_t)row * DKc + 4 * kq);
                const float vv[4] = {v.x, v.y, v.z, v.w};
#pragma unroll
                for (int j = 0; j < 4; j++) {
                    const int dk = 4 * kq + j;
                    QsPs[dk * 128 + (row ^ SW(dk))] = f2tf(vv[j] * LOG2E_SCALE);
                }
            }
        }
    }
    __syncthreads();

    // Q a-frags in registers
    uint32_t qa[8][4];
    {
        const int mr = 16 * warp;
#pragma unroll
        for (int ks = 0; ks < 8; ks++) {
            const int kb = 8 * ks;
            qa[ks][0] = QsPs[(kb + la) * 128 + ((mr + e) ^ SW(kb + la))];
            qa[ks][1] = QsPs[(kb + la) * 128 + ((mr + e + 8) ^ SW(kb + la))];
            qa[ks][2] = QsPs[(kb + la + 4) * 128 + ((mr + e) ^ SW(kb + la + 4))];
            qa[ks][3] = QsPs[(kb + la + 4) * 128 + ((mr + e + 8) ^ SW(kb + la + 4))];
        }
    }

    float o[8][4];
#pragma unroll
    for (int nb = 0; nb < 8; nb++)
#pragma unroll
        for (int t = 0; t < 4; t++) o[nb][t] = 0.f;
    float m0r = -1e30f, m1r = -1e30f, l0r = 0.f, l1r = 0.f;

    const int* flagp = gMaskFlag + qt * 32;

    for (int kt = 0; kt < 32; kt++) {
        const int k0 = kt * 64;
        __syncthreads();  // prev tile fully consumed (S reads of Ks, PV reads of Vs)

        // K tile -> Ks [dk][kv] transposed swizzled tf32
        {
            const int r = tid >> 2, qd = tid & 3;
#pragma unroll
            for (int i = 0; i < 4; i++) {
                const int kq = qd + 4 * i;
                float4 v = *(const float4*)(Kg + (size_t)(k0 + r) * DKc + 4 * kq);
                const float vv[4] = {v.x, v.y, v.z, v.w};
#pragma unroll
                for (int j = 0; j < 4; j++) {
                    const int dk = 4 * kq + j;
                    Ks[dk * 64 + (r ^ SW(dk))] = f2tf(vv[j]);
                }
            }
            // V tile -> Vs [kv][dk] stride 72, tf32
            const int rv = tid >> 4, c4 = (tid & 15) * 4;
#pragma unroll
            for (int i = 0; i < 4; i++) {
                const int row = rv + 16 * i;
                float4 v = *(const float4*)(Vg + (size_t)(k0 + row) * DKc + c4);
                Vs[row * 72 + c4 + 0] = f2tf(v.x);
                Vs[row * 72 + c4 + 1] = f2tf(v.y);
                Vs[row * 72 + c4 + 2] = f2tf(v.z);
                Vs[row * 72 + c4 + 3] = f2tf(v.w);
            }
        }
        __syncthreads();

        // S = Q K^T (log2 domain)
        float s[8][4];
#pragma unroll
        for (int nb = 0; nb < 8; nb++)
#pragma unroll
            for (int t = 0; t < 4; t++) s[nb][t] = 0.f;
#pragma unroll
        for (int ks = 0; ks < 8; ks++) {
            const int kb = 8 * ks;
#pragma unroll
            for (int nb = 0; nb < 8; nb++) {
                const int n = 8 * nb;
                const uint32_t b0 = Ks[(kb + la) * 64 + ((n + e) ^ SW(kb + la))];
                const uint32_t b1 = Ks[(kb + la + 4) * 64 + ((n + e) ^ SW(kb + la + 4))];
                mma8(s[nb], qa[ks], b0, b1);
            }
        }

        // mask (fast path: tile all ones)
        if (!flagp[kt]) {
#pragma unroll
            for (int nb = 0; nb < 8; nb++) {
                const int col = k0 + 8 * nb + 2 * la;
                const int* mp0 = mask + (size_t)(q0 + 16 * warp + e) * Sc + col;
                const int* mp1 = mask + (size_t)(q0 + 16 * warp + e + 8) * Sc + col;
                if (mp0[0] == 0) s[nb][0] = MASKVAL;
                if (mp0[1] == 0) s[nb][1] = MASKVAL;
                if (mp1[0] == 0) s[nb][2] = MASKVAL;
                if (mp1[1] == 0) s[nb][3] = MASKVAL;
            }
        }

        // online softmax (base-2)
        float mx0 = -1e30f, mx1 = -1e30f;
#pragma unroll
        for (int nb = 0; nb < 8; nb++) {
            mx0 = fmaxf(mx0, fmaxf(s[nb][0], s[nb][1]));
            mx1 = fmaxf(mx1, fmaxf(s[nb][2], s[nb][3]));
        }
        mx0 = fmaxf(mx0, __shfl_xor_sync(0xffffffffu, mx0, 1));
        mx0 = fmaxf(mx0, __shfl_xor_sync(0xffffffffu, mx0, 2));
        mx1 = fmaxf(mx1, __shfl_xor_sync(0xffffffffu, mx1, 1));
        mx1 = fmaxf(mx1, __shfl_xor_sync(0xffffffffu, mx1, 2));
        const float mn0 = fmaxf(m0r, mx0), mn1 = fmaxf(m1r, mx1);
        const float c0 = fexp2(m0r - mn0), c1 = fexp2(m1r - mn1);
        m0r = mn0; m1r = mn1;
        float sum0 = 0.f, sum1 = 0.f;
#pragma unroll
        for (int nb = 0; nb < 8; nb++) {
            s[nb][0] = fexp2(s[nb][0] - mn0); sum0 += s[nb][0];
            s[nb][1] = fexp2(s[nb][1] - mn0); sum0 += s[nb][1];
            s[nb][2] = fexp2(s[nb][2] - mn1); sum1 += s[nb][2];
            s[nb][3] = fexp2(s[nb][3] - mn1); sum1 += s[nb][3];
        }
        sum0 += __shfl_xor_sync(0xffffffffu, sum0, 1);
        sum0 += __shfl_xor_sync(0xffffffffu, sum0, 2);
        sum1 += __shfl_xor_sync(0xffffffffu, sum1, 1);
        sum1 += __shfl_xor_sync(0xffffffffu, sum1, 2);
        l0r = l0r * c0 + sum0;
        l1r = l1r * c1 + sum1;
#pragma unroll
        for (int nb = 0; nb < 8; nb++) {
            o[nb][0] *= c0; o[nb][1] *= c0; o[nb][2] *= c1; o[nb][3] *= c1;
        }

        // stage P (tf32) into warp-private rows of QsPs [q128][68]
        {
            const int r0 = 16 * warp + e, r1 = r0 + 8;
#pragma unroll
            for (int nb = 0; nb < 8; nb++) {
                const int col = 8 * nb + 2 * la;
                QsPs[r0 * 68 + col + 0] = f2tf(s[nb][0]);
                QsPs[r0 * 68 + col + 1] = f2tf(s[nb][1]);
                QsPs[r1 * 68 + col + 0] = f2tf(s[nb][2]);
                QsPs[r1 * 68 + col + 1] = f2tf(s[nb][3]);
            }
        }
        __syncwarp();

        // O += P @ V
#pragma unroll
        for (int ks = 0; ks < 8; ks++) {
            const int kb = 8 * ks;
            uint32_t pa[4];
            const int row = 16 * warp;
            pa[0] = QsPs[(row + e) * 68 + kb + la];
            pa[1] = QsPs[(row + e + 8) * 68 + kb + la];
            pa[2] = QsPs[(row + e) * 68 + kb + la + 4];
            pa[3] = QsPs[(row + e + 8) * 68 + kb + la + 4];
#pragma unroll
            for (int nb = 0; nb < 8; nb++) {
                const uint32_t b0 = Vs[(kb + la) * 72 + 8 * nb + e];
                const uint32_t b1 = Vs[(kb + la + 4) * 72 + 8 * nb + e];
                mma8(o[nb], pa, b0, b1);
            }
        }
    }

    // epilogue -> gA [b, s, h*64 + dk]
    const float inv0 = 1.f / l0r, inv1 = 1.f / l1r;
    const int b = bh >> 4, h = bh & 15;
    const int r0 = q0 + 16 * warp + e, r1 = r0 + 8;
#pragma unroll
    for (int nb = 0; nb < 8; nb++) {
        const int col = h * 64 + 8 * nb + 2 * la;
        *(float2*)(gA + (size_t)(b * Sc + r0) * Dc + col) =
            make_float2(o[nb][0] * inv0, o[nb][1] * inv0);
        *(float2*)(gA + (size_t)(b * Sc + r1) * Dc + col) =
            make_float2(o[nb][2] * inv1, o[nb][3] * inv1);
    }
}

// ---------------------------------------------------------------------------
extern "C" void kernel_launch(void* const* d_in, const int* in_sizes, int n_in,
                              void* d_out, int out_size) {
    const float* X  = (const float*)d_in[0];
    const int* mask = (const int*)d_in[1];
    const float* Wq = (const float*)d_in[2];
    const float* bq = (const float*)d_in[3];
    const float* Wk = (const float*)d_in[4];
    const float* bk = (const float*)d_in[5];
    const float* Wv = (const float*)d_in[6];
    const float* bv = (const float*)d_in[7];
    const float* Wo = (const float*)d_in[8];
    const float* bo = (const float*)d_in[9];
    float* out = (float*)d_out;

    const int flash_smem = (8704 + 4096 + 4608) * 4;  // 69632 B
    static int attr_set = 0;
    if (!attr_set) {
        cudaFuncSetAttribute(flash_kernel,
                             cudaFuncAttributeMaxDynamicSharedMemorySize, flash_smem);
        attr_set = 1;
    }

    mask_flags_kernel<<<512, 256>>>(mask);

    dim3 gq(Dc / 128, Mtot / 128, 3);
    qkv_kernel<<<gq, 256>>>(X, Wq, bq, Wk, bk, Wv, bv);

    dim3 gf(Sc / 128, 2 * Hc);
    flash_kernel<<<gf, 256, flash_smem>>>(mask);

    dim3 go(Dc / 128, Mtot / 128);
    oproj_kernel<<<go, 256>>>(Wo, bo, out);
}

// round 6
// speedup vs baseline: 1.1802x; 1.1802x over previous
#include <cuda_runtime.h>
#include <math.h>
#include <stdint.h>

#define Sc 2048
#define Dc 1024
#define Hc 16
#define DKc 64
#define Mtot 4096

#define LOG2E_SCALE 0.18033688011112042f     // 0.125 * log2(e)
#define MASKVAL     (-1.4426950408889634e9f) // -1e9 * log2(e)

// Scratch
__device__ float gQ[2 * Hc * Sc * DKc];   // [b,h,s,dk]
__device__ float gK[2 * Hc * Sc * DKc];
__device__ float gV[2 * Hc * Sc * DKc];
__device__ float gA[Mtot * Dc];           // attn out, [b,s,h*dk]
__device__ int gMaskFlag[16 * 32];        // [qtile128][ktile64] all-ones flags

#define SW(k) ((((k) & 3) ^ (((k) >> 2) & 3)) << 3)

__device__ __forceinline__ uint32_t f2tf(float f) {
    uint32_t u;
    asm("cvt.rna.tf32.f32 %0, %1;" : "=r"(u) : "f"(f));
    return u;
}
__device__ __forceinline__ float fexp2(float x) {
    float r;
    asm("ex2.approx.f32 %0, %1;" : "=f"(r) : "f"(x));
    return r;
}
__device__ __forceinline__ void mma8(float* c, const uint32_t* a, uint32_t b0, uint32_t b1) {
    asm volatile(
        "mma.sync.aligned.m16n8k8.row.col.f32.tf32.tf32.f32 "
        "{%0,%1,%2,%3},{%4,%5,%6,%7},{%8,%9},{%0,%1,%2,%3};\n"
        : "+f"(c[0]), "+f"(c[1]), "+f"(c[2]), "+f"(c[3])
        : "r"(a[0]), "r"(a[1]), "r"(a[2]), "r"(a[3]), "r"(b0), "r"(b1));
}

// ===========================================================================
// tf32 GEMM with fragment-native smem layouts.
// A-frag layout: word ((ks*8 + mi)*32 + lane'')*4 + (h + 2v)
//   lane'' = ((row&7)<<2) | (j ^ ((row&7)>>1 & 3));  load lane -> l ^ ((l>>3)&3)
// B-frag layout: word ((ks*16 + nb)*32 + lane'')*2 + v
//   lane'' extra-XORed by 3*(nb&1) to break the n-bit3 bank fold.
// 128x128 tile, BK=16, 256 threads, 8 warps (2m x 4n), warp tile 64x32.
// ===========================================================================
template <bool HEAD>
__device__ __forceinline__ void gemm_tf32(const float* __restrict__ A,
                                          const float* __restrict__ W,
                                          const float* __restrict__ bias,
                                          float* __restrict__ C) {
    __shared__ uint32_t As[2048];   // 2 ks * 8 mi * 32 lane * 4 idx
    __shared__ uint32_t Bs[2048];   // 2 ks * 16 nb * 32 lane * 2 v

    const int tid = threadIdx.x, lane = tid & 31, warp = tid >> 5;
    const int wm = warp >> 2, wn = warp & 3;
    const int m0 = blockIdx.y * 128, n0 = blockIdx.x * 128;

    const int row = tid >> 1;            // 0..127 (A row / B n-row)
    const int kh = (tid & 1) * 8;        // k-half within 16-chunk
    const int ksS = tid & 1;             // ks of this thread's stores
    const int r7 = row & 7;
    const int Xa = (r7 >> 1) & 3;
    const int miS = row >> 4, hA = (row >> 3) & 1;
    const int nbS = row >> 3;
    const int XB = Xa ^ (3 * (nbS & 1));

    // precomputed store word-indices for j=0 (j XORs into low lane bits)
    int aAddr[4], bAddr[4];
#pragma unroll
    for (int j = 0; j < 4; j++) {
        aAddr[j] = ((ksS * 8 + miS) * 32 + ((r7 << 2) | (j ^ Xa))) * 4 + hA;
        bAddr[j] = ((ksS * 16 + nbS) * 32 + ((r7 << 2) | (j ^ XB))) * 2;
    }

    const float* Ap = A + (size_t)(m0 + row) * Dc + kh;
    const float* Wp = W + (size_t)(n0 + row) * Dc + kh;

    const int lx = lane ^ ((lane >> 3) & 3);

    float acc[4][4][4];
#pragma unroll
    for (int mi = 0; mi < 4; mi++)
#pragma unroll
        for (int ni = 0; ni < 4; ni++)
#pragma unroll
            for (int t = 0; t < 4; t++) acc[mi][ni][t] = 0.f;

    float4 pa0 = *(const float4*)(Ap);
    float4 pa1 = *(const float4*)(Ap + 4);
    float4 pw0 = *(const float4*)(Wp);
    float4 pw1 = *(const float4*)(Wp + 4);

    for (int k0 = 0; k0 < Dc; k0 += 16) {
        __syncthreads();
        {
            const float a0[4] = {pa0.x, pa0.y, pa0.z, pa0.w};
            const float a1[4] = {pa1.x, pa1.y, pa1.z, pa1.w};
            const float w0[4] = {pw0.x, pw0.y, pw0.z, pw0.w};
            const float w1[4] = {pw1.x, pw1.y, pw1.z, pw1.w};
#pragma unroll
            for (int j = 0; j < 4; j++) {
                As[aAddr[j] + 0] = f2tf(a0[j]);   // v=0
                As[aAddr[j] + 2] = f2tf(a1[j]);   // v=1
                Bs[bAddr[j] + 0] = f2tf(w0[j]);
                Bs[bAddr[j] + 1] = f2tf(w1[j]);
            }
        }
        __syncthreads();

        if (k0 + 16 < Dc) {
            pa0 = *(const float4*)(Ap + k0 + 16);
            pa1 = *(const float4*)(Ap + k0 + 20);
            pw0 = *(const float4*)(Wp + k0 + 16);
            pw1 = *(const float4*)(Wp + k0 + 20);
        }

#pragma unroll
        for (int ks = 0; ks < 2; ks++) {
            uint4 af[4];
            uint2 bf[4];
#pragma unroll
            for (int mi = 0; mi < 4; mi++)
                af[mi] = *(const uint4*)&As[((ks * 8 + 4 * wm + mi) * 32 + lx) * 4];
#pragma unroll
            for (int ni = 0; ni < 4; ni++) {
                const int nb = 4 * wn + ni;
                const int lxb = lx ^ (3 * (nb & 1));
                bf[ni] = *(const uint2*)&Bs[((ks * 16 + nb) * 32 + lxb) * 2];
            }
#pragma unroll
            for (int mi = 0; mi < 4; mi++)
#pragma unroll
                for (int ni = 0; ni < 4; ni++)
                    mma8(acc[mi][ni], (const uint32_t*)&af[mi], bf[ni].x, bf[ni].y);
        }
    }

    const int e = lane >> 2, la = lane & 3;
#pragma unroll
    for (int mi = 0; mi < 4; mi++) {
#pragma unroll
        for (int ni = 0; ni < 4; ni++) {
            const int nc = n0 + 32 * wn + 8 * ni + 2 * la;
            const float b0 = bias[nc], b1 = bias[nc + 1];
#pragma unroll
            for (int half = 0; half < 2; half++) {
                const int mr = m0 + 64 * wm + 16 * mi + e + 8 * half;
                const float v0 = acc[mi][ni][2 * half] + b0;
                const float v1 = acc[mi][ni][2 * half + 1] + b1;
                if (HEAD) {
                    const int bb = mr >> 11;
                    const int s = mr & 2047;
                    const int h = nc >> 6, dk = nc & 63;
                    *(float2*)(C + (((size_t)(bb * Hc + h)) * Sc + s) * DKc + dk) =
                        make_float2(v0, v1);
                } else {
                    *(float2*)(C + (size_t)mr * Dc + nc) = make_float2(v0, v1);
                }
            }
        }
    }
}

__global__ __launch_bounds__(256, 2) void qkv_kernel(
    const float* __restrict__ X,
    const float* __restrict__ Wq, const float* __restrict__ bq,
    const float* __restrict__ Wk, const float* __restrict__ bk,
    const float* __restrict__ Wv, const float* __restrict__ bv) {
    const float* W = Wq;
    const float* bias = bq;
    float* out = gQ;
    if (blockIdx.z == 1) { W = Wk; bias = bk; out = gK; }
    else if (blockIdx.z == 2) { W = Wv; bias = bv; out = gV; }
    gemm_tf32<true>(X, W, bias, out);
}

__global__ __launch_bounds__(256, 2) void oproj_kernel(
    const float* __restrict__ Wo, const float* __restrict__ bo,
    float* __restrict__ out) {
    gemm_tf32<false>(gA, Wo, bo, out);
}

// ---------------------------------------------------------------------------
// Mask tile flags: flag = 1 iff the 128x64 mask tile is all nonzero.
// ---------------------------------------------------------------------------
__global__ __launch_bounds__(256) void mask_flags_kernel(const int* __restrict__ mask) {
    const int qt = blockIdx.x >> 5, kt = blockIdx.x & 31;
    const int tid = threadIdx.x;
    int ok = 1;
#pragma unroll
    for (int i = 0; i < 8; i++) {
        const int idx = tid + 256 * i;
        const int r = idx >> 4, c4 = (idx & 15) * 4;
        const int4 v = *(const int4*)(mask + (size_t)(qt * 128 + r) * Sc + kt * 64 + c4);
        ok &= (v.x != 0) & (v.y != 0) & (v.z != 0) & (v.w != 0);
    }
    ok = __syncthreads_and(ok);
    if (tid == 0) gMaskFlag[blockIdx.x] = ok;
}

// ---------------------------------------------------------------------------
// Flash attention, tf32 MMA. q-tile 128, kv-tile 64, 8 warps.
// K and V stored in fragment-native b-frag layouts (LDS.64 loads).
// smem (u32): QsPs[8704] | Ks[4096] | Vs[4096]  -> 67584 B, 2 CTAs/SM.
// ---------------------------------------------------------------------------
__global__ __launch_bounds__(256, 2) void flash_kernel(const int* __restrict__ mask) {
    extern __shared__ uint32_t smu[];
    uint32_t* QsPs = smu;                // 8704 u32
    uint32_t* Ks = smu + 8704;           // 4096 u32: ((ksd*8+nbk)*32+lane'')*2+v
    uint32_t* Vs = smu + 8704 + 4096;    // 4096 u32: ((ksv*8+nbd)*32+lane'')*2+v

    const int tid = threadIdx.x, lane = tid & 31, warp = tid >> 5;
    const int e = lane >> 2, la = lane & 3;
    const int qt = blockIdx.x, bh = blockIdx.y;
    const int q0 = qt * 128;
    const int lx = lane ^ ((lane >> 3) & 3);

    const float* Qg = gQ + (size_t)bh * Sc * DKc + (size_t)q0 * DKc;
    const float* Kg = gK + (size_t)bh * Sc * DKc;
    const float* Vg = gV + (size_t)bh * Sc * DKc;

    // Load + transpose Q -> QsPs (scaled, tf32), [dk][128] swizzled (prologue only)
    {
        const int r = tid >> 2, qd = tid & 3;
#pragma unroll
        for (int half = 0; half < 2; half++) {
            const int row = r + 64 * half;
#pragma unroll
            for (int i = 0; i < 4; i++) {
                const int kq = qd + 4 * i;
                float4 v = *(const float4*)(Qg + (size_t)row * DKc + 4 * kq);
                const float vv[4] = {v.x, v.y, v.z, v.w};
#pragma unroll
                for (int j = 0; j < 4; j++) {
                    const int dk = 4 * kq + j;
                    QsPs[dk * 128 + (row ^ SW(dk))] = f2tf(vv[j] * LOG2E_SCALE);
                }
            }
        }
    }
    __syncthreads();

    // Q a-frags in registers
    uint32_t qa[8][4];
    {
        const int mr = 16 * warp;
#pragma unroll
        for (int ks = 0; ks < 8; ks++) {
            const int kb = 8 * ks;
            qa[ks][0] = QsPs[(kb + la) * 128 + ((mr + e) ^ SW(kb + la))];
            qa[ks][1] = QsPs[(kb + la) * 128 + ((mr + e + 8) ^ SW(kb + la))];
            qa[ks][2] = QsPs[(kb + la + 4) * 128 + ((mr + e) ^ SW(kb + la + 4))];
            qa[ks][3] = QsPs[(kb + la + 4) * 128 + ((mr + e + 8) ^ SW(kb + la + 4))];
        }
    }

    float o[8][4];
#pragma unroll
    for (int nb = 0; nb < 8; nb++)
#pragma unroll
        for (int t = 0; t < 4; t++) o[nb][t] = 0.f;
    float m0r = -1e30f, m1r = -1e30f, l0r = 0.f, l1r = 0.f;

    const int* flagp = gMaskFlag + qt * 32;

    // K-store constants: thread covers kv-row r, dk = 4*(qd+4i)+j
    const int rK = tid >> 2, qdK = tid & 3;
    const int XK = ((rK & 7) >> 1) & 3;
    const int nbK = rK >> 3;
    // V-store constants: thread covers kv-rows rv+16i, dk = c4+j
    const int rvV = tid >> 4, c4V = (tid & 15) * 4;

    for (int kt = 0; kt < 32; kt++) {
        const int k0 = kt * 64;
        __syncthreads();

        // K tile -> Ks fragment layout
#pragma unroll
        for (int i = 0; i < 4; i++) {
            const int kq = qdK + 4 * i;
            const int ksd = kq >> 1, vK = kq & 1;
            float4 v = *(const float4*)(Kg + (size_t)(k0 + rK) * DKc + 4 * kq);
            const float vv[4] = {v.x, v.y, v.z, v.w};
#pragma unroll
            for (int j = 0; j < 4; j++)
                Ks[((ksd * 8 + nbK) * 32 + (((rK & 7) << 2) | (j ^ XK))) * 2 + vK] =
                    f2tf(vv[j]);
        }
        // V tile -> Vs fragment layout
#pragma unroll
        for (int i = 0; i < 4; i++) {
            const int row = rvV + 16 * i;              // kv
            const int ksv = row >> 3, vV = (row >> 2) & 1, k3 = row & 3;
            float4 v = *(const float4*)(Vg + (size_t)(k0 + row) * DKc + c4V);
            const float vv[4] = {v.x, v.y, v.z, v.w};
#pragma unroll
            for (int j = 0; j < 4; j++) {
                const int dk = c4V + j;
                const int nbd = dk >> 3, d7 = dk & 7;
                const int XV = (nbd ^ (d7 >> 1)) & 3;
                Vs[((ksv * 8 + nbd) * 32 + ((d7 << 2) | (k3 ^ XV))) * 2 + vV] =
                    f2tf(vv[j]);
            }
        }
        __syncthreads();

        // S = Q K^T (log2 domain)
        float s[8][4];
#pragma unroll
        for (int nb = 0; nb < 8; nb++)
#pragma unroll
            for (int t = 0; t < 4; t++) s[nb][t] = 0.f;
#pragma unroll
        for (int ks = 0; ks < 8; ks++) {
#pragma unroll
            for (int nb = 0; nb < 8; nb++) {
                const uint2 b = *(const uint2*)&Ks[((ks * 8 + nb) * 32 + lx) * 2];
                mma8(s[nb], qa[ks], b.x, b.y);
            }
        }

        // mask (fast path: tile all ones)
        if (!flagp[kt]) {
#pragma unroll
            for (int nb = 0; nb < 8; nb++) {
                const int col = k0 + 8 * nb + 2 * la;
                const int* mp0 = mask + (size_t)(q0 + 16 * warp + e) * Sc + col;
                const int* mp1 = mask + (size_t)(q0 + 16 * warp + e + 8) * Sc + col;
                if (mp0[0] == 0) s[nb][0] = MASKVAL;
                if (mp0[1] == 0) s[nb][1] = MASKVAL;
                if (mp1[0] == 0) s[nb][2] = MASKVAL;
                if (mp1[1] == 0) s[nb][3] = MASKVAL;
            }
        }

        // online softmax (base-2)
        float mx0 = -1e30f, mx1 = -1e30f;
#pragma unroll
        for (int nb = 0; nb < 8; nb++) {
            mx0 = fmaxf(mx0, fmaxf(s[nb][0], s[nb][1]));
            mx1 = fmaxf(mx1, fmaxf(s[nb][2], s[nb][3]));
        }
        mx0 = fmaxf(mx0, __shfl_xor_sync(0xffffffffu, mx0, 1));
        mx0 = fmaxf(mx0, __shfl_xor_sync(0xffffffffu, mx0, 2));
        mx1 = fmaxf(mx1, __shfl_xor_sync(0xffffffffu, mx1, 1));
        mx1 = fmaxf(mx1, __shfl_xor_sync(0xffffffffu, mx1, 2));
        const float mn0 = fmaxf(m0r, mx0), mn1 = fmaxf(m1r, mx1);
        const float c0 = fexp2(m0r - mn0), c1 = fexp2(m1r - mn1);
        m0r = mn0; m1r = mn1;
        float sum0 = 0.f, sum1 = 0.f;
#pragma unroll
        for (int nb = 0; nb < 8; nb++) {
            s[nb][0] = fexp2(s[nb][0] - mn0); sum0 += s[nb][0];
            s[nb][1] = fexp2(s[nb][1] - mn0); sum0 += s[nb][1];
            s[nb][2] = fexp2(s[nb][2] - mn1); sum1 += s[nb][2];
            s[nb][3] = fexp2(s[nb][3] - mn1); sum1 += s[nb][3];
        }
        sum0 += __shfl_xor_sync(0xffffffffu, sum0, 1);
        sum0 += __shfl_xor_sync(0xffffffffu, sum0, 2);
        sum1 += __shfl_xor_sync(0xffffffffu, sum1, 1);
        sum1 += __shfl_xor_sync(0xffffffffu, sum1, 2);
        l0r = l0r * c0 + sum0;
        l1r = l1r * c1 + sum1;
#pragma unroll
        for (int nb = 0; nb < 8; nb++) {
            o[nb][0] *= c0; o[nb][1] *= c0; o[nb][2] *= c1; o[nb][3] *= c1;
        }

        // stage P (tf32) into warp-private rows of QsPs [q128][68]
        {
            const int r0 = 16 * warp + e, r1 = r0 + 8;
#pragma unroll
            for (int nb = 0; nb < 8; nb++) {
                const int col = 8 * nb + 2 * la;
                QsPs[r0 * 68 + col + 0] = f2tf(s[nb][0]);
                QsPs[r0 * 68 + col + 1] = f2tf(s[nb][1]);
                QsPs[r1 * 68 + col + 0] = f2tf(s[nb][2]);
                QsPs[r1 * 68 + col + 1] = f2tf(s[nb][3]);
            }
        }
        __syncwarp();

        // O += P @ V
#pragma unroll
        for (int ks = 0; ks < 8; ks++) {
            const int kb = 8 * ks;
            uint32_t pa[4];
            const int rw = 16 * warp;
            pa[0] = QsPs[(rw + e) * 68 + kb + la];
            pa[1] = QsPs[(rw + e + 8) * 68 + kb + la];
            pa[2] = QsPs[(rw + e) * 68 + kb + la + 4];
            pa[3] = QsPs[(rw + e + 8) * 68 + kb + la + 4];
#pragma unroll
            for (int nb = 0; nb < 8; nb++) {
                const int lxv = lane ^ ((nb ^ (lane >> 3)) & 3);
                const uint2 b = *(const uint2*)&Vs[((ks * 8 + nb) * 32 + lxv) * 2];
                mma8(o[nb], pa, b.x, b.y);
            }
        }
    }

    // epilogue -> gA [b, s, h*64 + dk]
    const float inv0 = 1.f / l0r, inv1 = 1.f / l1r;
    const int b = bh >> 4, h = bh & 15;
    const int r0 = q0 + 16 * warp + e, r1 = r0 + 8;
#pragma unroll
    for (int nb = 0; nb < 8; nb++) {
        const int col = h * 64 + 8 * nb + 2 * la;
        *(float2*)(gA + (size_t)(b * Sc + r0) * Dc + col) =
            make_float2(o[nb][0] * inv0, o[nb][1] * inv0);
        *(float2*)(gA + (size_t)(b * Sc + r1) * Dc + col) =
            make_float2(o[nb][2] * inv1, o[nb][3] * inv1);
    }
}

// ---------------------------------------------------------------------------
extern "C" void kernel_launch(void* const* d_in, const int* in_sizes, int n_in,
                              void* d_out, int out_size) {
    const float* X  = (const float*)d_in[0];
    const int* mask = (const int*)d_in[1];
    const float* Wq = (const float*)d_in[2];
    const float* bq = (const float*)d_in[3];
    const float* Wk = (const float*)d_in[4];
    const float* bk = (const float*)d_in[5];
    const float* Wv = (const float*)d_in[6];
    const float* bv = (const float*)d_in[7];
    const float* Wo = (const float*)d_in[8];
    const float* bo = (const float*)d_in[9];
    float* out = (float*)d_out;

    const int flash_smem = (8704 + 4096 + 4096) * 4;  // 67584 B
    static int attr_set = 0;
    if (!attr_set) {
        cudaFuncSetAttribute(flash_kernel,
                             cudaFuncAttributeMaxDynamicSharedMemorySize, flash_smem);
        attr_set = 1;
    }

    mask_flags_kernel<<<512, 256>>>(mask);

    dim3 gq(Dc / 128, Mtot / 128, 3);
    qkv_kernel<<<gq, 256>>>(X, Wq, bq, Wk, bk, Wv, bv);

    dim3 gf(Sc / 128, 2 * Hc);
    flash_kernel<<<gf, 256, flash_smem>>>(mask);

    dim3 go(Dc / 128, Mtot / 128);
    oproj_kernel<<<go, 256>>>(Wo, bo, out);
}